// round 3
// baseline (speedup 1.0000x reference)
#include <cuda_runtime.h>
#include <math.h>

// Problem constants (fixed shapes)
#define Bn  8
#define Cn  32
#define Tn  4096
#define Kn  9
#define COn 32
#define Mc  12   // fast-pass candidate count (margin over Kn=9)

// Scratch (no allocations allowed in kernel_launch)
__device__ double g_xn64[Bn * Tn * Cn];  // f64 normalized, token-major [b][t][c]
__device__ float  g_xn32[Bn * Tn * Cn];  // f32 rounding of g_xn64
__device__ float  g_xf[Bn * Tn * Cn];    // raw features f32, token-major
__device__ int    g_cand[Bn * Tn * Mc];  // fast-pass candidate indices
__device__ float  g_vals[Bn * Tn * Kn];  // final top-K vals (sorted desc)
__device__ int    g_idx[Bn * Tn * Kn];   // final top-K indices

// Packed dual-fp32 FMA (each lane independent IEEE fp32 fma)
__device__ __forceinline__ float2 fma_f32x2(float2 a, float2 b, float2 c) {
    float2 d;
    asm("fma.rn.f32x2 %0, %1, %2, %3;"
        : "=l"(reinterpret_cast<unsigned long long&>(d))
        : "l"(reinterpret_cast<unsigned long long&>(a)),
          "l"(reinterpret_cast<unsigned long long&>(b)),
          "l"(reinterpret_cast<unsigned long long&>(c)));
    return d;
}

// ---------------------------------------------------------------------------
// Kernel 1: f64 per-token L2 norm + normalize; outputs f64 + f32 copies.
// ---------------------------------------------------------------------------
__global__ __launch_bounds__(256) void prep_kernel(const float* __restrict__ x) {
    int b = blockIdx.y;
    int t = blockIdx.x * 256 + threadIdx.x;
    const float* xb = x + (size_t)b * Cn * Tn;

    float v[Cn];
    double ss = 0.0;
#pragma unroll
    for (int c = 0; c < Cn; c++) {
        float f = xb[(size_t)c * Tn + t];
        v[c] = f;
        ss = fma((double)f, (double)f, ss);
    }
    double nrm = fmax(sqrt(ss), 1e-12);
    double rin = 1.0 / nrm;   // fast-pass only; f64 path divides exactly

    size_t base = ((size_t)b * Tn + t) * Cn;
    double* p64 = g_xn64 + base;
    float4* pf = reinterpret_cast<float4*>(g_xf + base);
    float4* pn = reinterpret_cast<float4*>(g_xn32 + base);
#pragma unroll
    for (int c = 0; c < Cn; c += 4) {
        double d0 = (double)v[c] / nrm, d1 = (double)v[c + 1] / nrm;
        double d2 = (double)v[c + 2] / nrm, d3 = (double)v[c + 3] / nrm;
        p64[c] = d0; p64[c + 1] = d1; p64[c + 2] = d2; p64[c + 3] = d3;
        pf[c / 4] = make_float4(v[c], v[c + 1], v[c + 2], v[c + 3]);
        pn[c / 4] = make_float4((float)d0, (float)d1, (float)d2, (float)d3);
        (void)rin;
    }
}

// ---------------------------------------------------------------------------
// Kernel 2: fast fp32 similarity pass -> top-12 candidate indices per query.
// One thread per query; keys pair-interleaved in smem; two keys per packed
// f32x2 fma; LDS.128 fetches two channel-pairs at once. Accuracy only needs
// to preserve the candidate SET (margin ~1e-6 error vs ~1e-2 rank spacing).
// ---------------------------------------------------------------------------
#define TKEY 256

__global__ __launch_bounds__(128) void topk_kernel() {
    int b = blockIdx.y;
    int q = blockIdx.x * 128 + threadIdx.x;
    const float* xnb = g_xn32 + (size_t)b * Tn * Cn;

    float2 qd[Cn];  // query value duplicated into both packed lanes
    {
        const float4* qp = reinterpret_cast<const float4*>(xnb + (size_t)q * Cn);
#pragma unroll
        for (int c4 = 0; c4 < Cn / 4; c4++) {
            float4 f = qp[c4];
            qd[c4 * 4 + 0] = make_float2(f.x, f.x);
            qd[c4 * 4 + 1] = make_float2(f.y, f.y);
            qd[c4 * 4 + 2] = make_float2(f.z, f.z);
            qd[c4 * 4 + 3] = make_float2(f.w, f.w);
        }
    }

    float v[Mc];
    int   id[Mc];
#pragma unroll
    for (int p = 0; p < Mc; p++) { v[p] = -2.f; id[p] = 0; }

    // row stride 34 float2 = 272B (16B aligned) for float4 reads
    __shared__ float2 ks2[TKEY / 2][Cn + 2];

    for (int tile = 0; tile < Tn; tile += TKEY) {
        __syncthreads();
        for (int r = threadIdx.x; r < TKEY; r += 128) {
            const float4* kp = reinterpret_cast<const float4*>(xnb + (size_t)(tile + r) * Cn);
            float* dst = &ks2[r >> 1][0].x + (r & 1);
#pragma unroll
            for (int c4 = 0; c4 < Cn / 4; c4++) {
                float4 f = kp[c4];
                dst[(c4 * 4 + 0) * 2] = f.x;
                dst[(c4 * 4 + 1) * 2] = f.y;
                dst[(c4 * 4 + 2) * 2] = f.z;
                dst[(c4 * 4 + 3) * 2] = f.w;
            }
        }
        __syncthreads();

#pragma unroll 2
        for (int p = 0; p < TKEY / 2; p++) {
            const float4* kr = reinterpret_cast<const float4*>(&ks2[p][0]);
            float2 accA = make_float2(0.f, 0.f), accB = make_float2(0.f, 0.f);
#pragma unroll
            for (int c4 = 0; c4 < Cn / 4; c4++) {  // c4 covers channels 2*c4, 2*c4+1
                float4 k0 = kr[2 * c4];
                float4 k1 = kr[2 * c4 + 1];
                accA = fma_f32x2(qd[4 * c4 + 0], make_float2(k0.x, k0.y), accA);
                accB = fma_f32x2(qd[4 * c4 + 1], make_float2(k0.z, k0.w), accB);
                accA = fma_f32x2(qd[4 * c4 + 2], make_float2(k1.x, k1.y), accA);
                accB = fma_f32x2(qd[4 * c4 + 3], make_float2(k1.z, k1.w), accB);
            }
            float s0 = accA.x + accB.x;
            float s1 = accA.y + accB.y;

            if (s0 > v[Mc - 1]) {
                v[Mc - 1] = s0; id[Mc - 1] = tile + 2 * p;
#pragma unroll
                for (int pp = Mc - 1; pp > 0; --pp) {
                    if (v[pp] > v[pp - 1]) {
                        float tv = v[pp]; v[pp] = v[pp - 1]; v[pp - 1] = tv;
                        int   ti = id[pp]; id[pp] = id[pp - 1]; id[pp - 1] = ti;
                    }
                }
            }
            if (s1 > v[Mc - 1]) {
                v[Mc - 1] = s1; id[Mc - 1] = tile + 2 * p + 1;
#pragma unroll
                for (int pp = Mc - 1; pp > 0; --pp) {
                    if (v[pp] > v[pp - 1]) {
                        float tv = v[pp]; v[pp] = v[pp - 1]; v[pp - 1] = tv;
                        int   ti = id[pp]; id[pp] = id[pp - 1]; id[pp - 1] = ti;
                    }
                }
            }
        }
    }

    size_t obase = ((size_t)b * Tn + q) * Mc;
#pragma unroll
    for (int p = 0; p < Mc; p++) g_cand[obase + p] = id[p];
}

// ---------------------------------------------------------------------------
// Kernel 3: exact f64 rescore of the 12 candidates; clip; stable sort by
// (value desc, index asc) == jax.lax.top_k semantics; emit top-9.
// ---------------------------------------------------------------------------
__global__ __launch_bounds__(128) void rescore_kernel() {
    int b = blockIdx.y;
    int q = blockIdx.x * 128 + threadIdx.x;
    const double* xnb = g_xn64 + (size_t)b * Tn * Cn;

    double qv[Cn];
    const double* xq = xnb + (size_t)q * Cn;
#pragma unroll
    for (int c = 0; c < Cn; c++) qv[c] = xq[c];

    size_t cbase = ((size_t)b * Tn + q) * Mc;
    double sv[Mc];
    int    si[Mc];
#pragma unroll
    for (int m = 0; m < Mc; m++) {
        int ii = g_cand[cbase + m];
        const double* xs = xnb + (size_t)ii * Cn;
        double a0 = 0.0, a1 = 0.0;
#pragma unroll
        for (int c = 0; c < Cn; c += 2) {
            a0 = fma(qv[c], xs[c], a0);
            a1 = fma(qv[c + 1], xs[c + 1], a1);
        }
        double s = fmin(fmax(a0 + a1, -1.0), 1.0);
        sv[m] = s; si[m] = ii;
    }

    // insertion sort: value desc, tie -> lower index first
#pragma unroll
    for (int i = 1; i < Mc; i++) {
#pragma unroll
        for (int j = Mc - 1; j >= 1; j--) {
            bool sw = (sv[j] > sv[j - 1]) ||
                      (sv[j] == sv[j - 1] && si[j] < si[j - 1]);
            if (sw) {
                double tv = sv[j]; sv[j] = sv[j - 1]; sv[j - 1] = tv;
                int    ti = si[j]; si[j] = si[j - 1]; si[j - 1] = ti;
            }
        }
    }

    size_t obase = ((size_t)b * Tn + q) * Kn;
#pragma unroll
    for (int p = 0; p < Kn; p++) {
        g_vals[obase + p] = (float)sv[p];
        g_idx[obase + p]  = si[p];
    }
}

// ---------------------------------------------------------------------------
// Kernel 4: gather neighbors, scale by vals, contract with conv weight.
// ---------------------------------------------------------------------------
__global__ __launch_bounds__(256) void conv_kernel(const float* __restrict__ w,
                                                   const float* __restrict__ bias,
                                                   float* __restrict__ out) {
    __shared__ float w_s[Cn * Kn * COn];     // [(c*9+k)*32 + o]
    __shared__ float prime[8][Kn][Cn];       // per-warp [k][c]
    __shared__ float bias_s[COn];

    int b = blockIdx.y;

    for (int i = threadIdx.x; i < COn * Cn * Kn; i += 256) {
        int o = i / (Cn * Kn);
        int rem = i % (Cn * Kn);
        int c = rem / Kn;
        int k = rem % Kn;
        w_s[(c * Kn + k) * COn + o] = w[i];
    }
    if (threadIdx.x < COn) bias_s[threadIdx.x] = bias[threadIdx.x];
    __syncthreads();

    int warp = threadIdx.x >> 5;
    int lane = threadIdx.x & 31;
    const float* xfb = g_xf + (size_t)b * Tn * Cn;

#pragma unroll 1
    for (int tt = 0; tt < 4; tt++) {
        int t = blockIdx.x * 32 + tt * 8 + warp;
        size_t base = ((size_t)b * Tn + t) * Kn;

        __syncwarp();
#pragma unroll
        for (int k = 0; k < Kn; k++) {
            float vk = g_vals[base + k];
            int   ik = g_idx[base + k];
            prime[warp][k][lane] = vk * xfb[(size_t)ik * Cn + lane];
        }
        __syncwarp();

        float acc = bias_s[lane];
#pragma unroll
        for (int c = 0; c < Cn; c++) {
#pragma unroll
            for (int k = 0; k < Kn; k++) {
                acc = fmaf(prime[warp][k][c], w_s[(c * Kn + k) * COn + lane], acc);
            }
        }
        out[((size_t)b * COn + lane) * Tn + t] = acc;
    }
}

// ---------------------------------------------------------------------------
extern "C" void kernel_launch(void* const* d_in, const int* in_sizes, int n_in,
                              void* d_out, int out_size) {
    const float* x    = (const float*)d_in[0];  // [8,32,64,64]
    const float* w    = (const float*)d_in[1];  // [32,32,9]
    const float* bias = (const float*)d_in[2];  // [32]
    float* out = (float*)d_out;                 // [8,32,64,64]

    prep_kernel<<<dim3(Tn / 256, Bn), 256>>>(x);
    topk_kernel<<<dim3(Tn / 128, Bn), 128>>>();
    rescore_kernel<<<dim3(Tn / 128, Bn), 128>>>();
    conv_kernel<<<dim3(Tn / 32, Bn), 256>>>(w, bias, out);
}

// round 4
// speedup vs baseline: 1.1452x; 1.1452x over previous
#include <cuda_runtime.h>
#include <math.h>

// Problem constants (fixed shapes)
#define Bn  8
#define Cn  32
#define Tn  4096
#define Kn  9
#define COn 32
#define Mc  12   // fast-pass candidate count (margin over Kn=9)

// Scratch (no allocations allowed in kernel_launch)
__device__ double g_xn64[Bn * Tn * Cn];  // f64 normalized, token-major [b][t][c]
__device__ float  g_xn32[Bn * Tn * Cn];  // f32 rounding of g_xn64
__device__ float  g_xf[Bn * Tn * Cn];    // raw features f32, token-major
__device__ float  g_wT[Cn * Kn * COn];   // weight transposed [(c*9+k)*32+o]
__device__ int    g_cand[Bn * Tn * Mc];  // fast-pass candidate indices
__device__ float  g_vals[Bn * Tn * Kn];  // final top-K vals (sorted desc)
__device__ int    g_idx[Bn * Tn * Kn];   // final top-K indices

// ---------------------------------------------------------------------------
// Kernel 1: f64 per-token L2 norm + normalize (1 DDIV + DMULs).
// ---------------------------------------------------------------------------
__global__ __launch_bounds__(256) void prep_kernel(const float* __restrict__ x) {
    int b = blockIdx.y;
    int t = blockIdx.x * 256 + threadIdx.x;
    const float* xb = x + (size_t)b * Cn * Tn;

    float v[Cn];
    double ss = 0.0;
#pragma unroll
    for (int c = 0; c < Cn; c++) {
        float f = xb[(size_t)c * Tn + t];
        v[c] = f;
        ss = fma((double)f, (double)f, ss);
    }
    double rin = 1.0 / fmax(sqrt(ss), 1e-12);

    size_t base = ((size_t)b * Tn + t) * Cn;
    double* p64 = g_xn64 + base;
    float4* pf = reinterpret_cast<float4*>(g_xf + base);
    float4* pn = reinterpret_cast<float4*>(g_xn32 + base);
#pragma unroll
    for (int c = 0; c < Cn; c += 4) {
        double d0 = (double)v[c] * rin, d1 = (double)v[c + 1] * rin;
        double d2 = (double)v[c + 2] * rin, d3 = (double)v[c + 3] * rin;
        p64[c] = d0; p64[c + 1] = d1; p64[c + 2] = d2; p64[c + 3] = d3;
        pf[c / 4] = make_float4(v[c], v[c + 1], v[c + 2], v[c + 3]);
        pn[c / 4] = make_float4((float)d0, (float)d1, (float)d2, (float)d3);
    }
}

// ---------------------------------------------------------------------------
// Kernel 1b: transpose conv weight to [(c*9+k)*32 + o] for coalesced reads.
// ---------------------------------------------------------------------------
__global__ void wt_kernel(const float* __restrict__ w) {
    int i = blockIdx.x * 256 + threadIdx.x;
    if (i < COn * Cn * Kn) {
        int o = i / (Cn * Kn);
        int rem = i % (Cn * Kn);
        int c = rem / Kn;
        int k = rem % Kn;
        g_wT[(c * Kn + k) * COn + o] = w[i];
    }
}

// ---------------------------------------------------------------------------
// Kernel 2: fast fp32 similarity pass -> top-12 candidate indices per query.
// One thread per query, plain scalar FFMA, 4 accumulator chains per key pair.
// Keys row-major in smem (128B rows); all lanes read the same key row ->
// broadcast, conflict-free. Accuracy only needs to preserve the candidate
// SET (fp32 error ~1e-6 vs rank-9..12 spacing ~1e-2).
// ---------------------------------------------------------------------------
#define TKEY 128

__global__ __launch_bounds__(128) void topk_kernel() {
    int b = blockIdx.y;
    int q = blockIdx.x * 128 + threadIdx.x;
    const float* xnb = g_xn32 + (size_t)b * Tn * Cn;

    float4 qv4[Cn / 4];
    {
        const float4* qp = reinterpret_cast<const float4*>(xnb + (size_t)q * Cn);
#pragma unroll
        for (int c4 = 0; c4 < Cn / 4; c4++) qv4[c4] = qp[c4];
    }

    float v[Mc];
    int   id[Mc];
#pragma unroll
    for (int p = 0; p < Mc; p++) { v[p] = -2.f; id[p] = 0; }

    __shared__ float4 ks[TKEY][Cn / 4];   // 16 KB, row-major

    for (int tile = 0; tile < Tn; tile += TKEY) {
        __syncthreads();
        // coalesced loader: consecutive tids -> consecutive quads of a row
        const float4* src = reinterpret_cast<const float4*>(xnb + (size_t)tile * Cn);
#pragma unroll
        for (int i = threadIdx.x; i < TKEY * (Cn / 4); i += 128) {
            (&ks[0][0])[i] = src[i];
        }
        __syncthreads();

#pragma unroll 2
        for (int j = 0; j < TKEY; j += 2) {
            const float4* r0 = &ks[j][0];
            const float4* r1 = &ks[j + 1][0];
            float s0a = 0.f, s0b = 0.f, s1a = 0.f, s1b = 0.f;
#pragma unroll
            for (int c4 = 0; c4 < Cn / 4; c4++) {
                float4 f0 = r0[c4];
                float4 f1 = r1[c4];
                float4 qq = qv4[c4];
                s0a = fmaf(qq.x, f0.x, s0a);
                s0b = fmaf(qq.y, f0.y, s0b);
                s1a = fmaf(qq.x, f1.x, s1a);
                s1b = fmaf(qq.y, f1.y, s1b);
                s0a = fmaf(qq.z, f0.z, s0a);
                s0b = fmaf(qq.w, f0.w, s0b);
                s1a = fmaf(qq.z, f1.z, s1a);
                s1b = fmaf(qq.w, f1.w, s1b);
            }
            float s0 = s0a + s0b;
            float s1 = s1a + s1b;

            if (s0 > v[Mc - 1]) {
                v[Mc - 1] = s0; id[Mc - 1] = tile + j;
#pragma unroll
                for (int pp = Mc - 1; pp > 0; --pp) {
                    if (v[pp] > v[pp - 1]) {
                        float tv = v[pp]; v[pp] = v[pp - 1]; v[pp - 1] = tv;
                        int   ti = id[pp]; id[pp] = id[pp - 1]; id[pp - 1] = ti;
                    }
                }
            }
            if (s1 > v[Mc - 1]) {
                v[Mc - 1] = s1; id[Mc - 1] = tile + j + 1;
#pragma unroll
                for (int pp = Mc - 1; pp > 0; --pp) {
                    if (v[pp] > v[pp - 1]) {
                        float tv = v[pp]; v[pp] = v[pp - 1]; v[pp - 1] = tv;
                        int   ti = id[pp]; id[pp] = id[pp - 1]; id[pp - 1] = ti;
                    }
                }
            }
        }
    }

    size_t obase = ((size_t)b * Tn + q) * Mc;
#pragma unroll
    for (int p = 0; p < Mc; p++) g_cand[obase + p] = id[p];
}

// ---------------------------------------------------------------------------
// Kernel 3: exact f64 rescore of the 12 candidates; clip; stable sort by
// (value desc, index asc) == jax.lax.top_k semantics; emit top-9.
// ---------------------------------------------------------------------------
__global__ __launch_bounds__(128) void rescore_kernel() {
    int b = blockIdx.y;
    int q = blockIdx.x * 128 + threadIdx.x;
    const double* xnb = g_xn64 + (size_t)b * Tn * Cn;

    double qv[Cn];
    {
        const double2* xq = reinterpret_cast<const double2*>(xnb + (size_t)q * Cn);
#pragma unroll
        for (int c2 = 0; c2 < Cn / 2; c2++) {
            double2 d = xq[c2];
            qv[2 * c2] = d.x; qv[2 * c2 + 1] = d.y;
        }
    }

    size_t cbase = ((size_t)b * Tn + q) * Mc;
    double sv[Mc];
    int    si[Mc];
#pragma unroll
    for (int m = 0; m < Mc; m++) {
        int ii = g_cand[cbase + m];
        const double2* xs = reinterpret_cast<const double2*>(xnb + (size_t)ii * Cn);
        double a0 = 0.0, a1 = 0.0;
#pragma unroll
        for (int c2 = 0; c2 < Cn / 2; c2++) {
            double2 d = xs[c2];
            a0 = fma(qv[2 * c2], d.x, a0);
            a1 = fma(qv[2 * c2 + 1], d.y, a1);
        }
        double s = fmin(fmax(a0 + a1, -1.0), 1.0);
        sv[m] = s; si[m] = ii;
    }

    // insertion sort: value desc, tie -> lower index first
#pragma unroll
    for (int i = 1; i < Mc; i++) {
#pragma unroll
        for (int j = Mc - 1; j >= 1; j--) {
            bool sw = (sv[j] > sv[j - 1]) ||
                      (sv[j] == sv[j - 1] && si[j] < si[j - 1]);
            if (sw) {
                double tv = sv[j]; sv[j] = sv[j - 1]; sv[j - 1] = tv;
                int    ti = si[j]; si[j] = si[j - 1]; si[j - 1] = ti;
            }
        }
    }

    size_t obase = ((size_t)b * Tn + q) * Kn;
#pragma unroll
    for (int p = 0; p < Kn; p++) {
        g_vals[obase + p] = (float)sv[p];
        g_idx[obase + p]  = si[p];
    }
}

// ---------------------------------------------------------------------------
// Kernel 4: gather + conv. Warp handles 4 tokens concurrently; weight read
// once per (c,k) from L1-resident transposed global (coalesced, reused
// across the 4 tokens); prime staged in smem, broadcast reads.
// ---------------------------------------------------------------------------
__global__ __launch_bounds__(256) void conv_kernel(const float* __restrict__ bias,
                                                   float* __restrict__ out) {
    __shared__ float prime[8][4][Kn][Cn];   // 36.9 KB

    int b = blockIdx.y;
    int warp = threadIdx.x >> 5;
    int lane = threadIdx.x & 31;
    const float* xfb = g_xf + (size_t)b * Tn * Cn;

    int t0 = blockIdx.x * 32 + warp * 4;
    size_t vbase = ((size_t)b * Tn + t0) * Kn;

    // gather: 36 rows (4 tokens x 9 neighbors)
#pragma unroll
    for (int m = 0; m < 4 * Kn; m++) {
        int tt = m / Kn, k = m % Kn;
        float vk = g_vals[vbase + tt * Kn + k];
        int   ik = g_idx[vbase + tt * Kn + k];
        prime[warp][tt][k][lane] = vk * xfb[(size_t)ik * Cn + lane];
    }
    __syncwarp();

    float bsl = bias[lane];
    float a0 = bsl, a1 = bsl, a2 = bsl, a3 = bsl;
#pragma unroll
    for (int c = 0; c < Cn; c++) {
#pragma unroll
        for (int k = 0; k < Kn; k++) {
            float wv = g_wT[(c * Kn + k) * COn + lane];
            a0 = fmaf(prime[warp][0][k][c], wv, a0);
            a1 = fmaf(prime[warp][1][k][c], wv, a1);
            a2 = fmaf(prime[warp][2][k][c], wv, a2);
            a3 = fmaf(prime[warp][3][k][c], wv, a3);
        }
    }
    size_t ob = ((size_t)b * COn + lane) * Tn + t0;
    out[ob + 0] = a0; out[ob + 1] = a1; out[ob + 2] = a2; out[ob + 3] = a3;
}

// ---------------------------------------------------------------------------
extern "C" void kernel_launch(void* const* d_in, const int* in_sizes, int n_in,
                              void* d_out, int out_size) {
    const float* x    = (const float*)d_in[0];  // [8,32,64,64]
    const float* w    = (const float*)d_in[1];  // [32,32,9]
    const float* bias = (const float*)d_in[2];  // [32]
    float* out = (float*)d_out;                 // [8,32,64,64]

    prep_kernel<<<dim3(Tn / 256, Bn), 256>>>(x);
    wt_kernel<<<(COn * Cn * Kn + 255) / 256, 256>>>(w);
    topk_kernel<<<dim3(Tn / 128, Bn), 128>>>();
    rescore_kernel<<<dim3(Tn / 128, Bn), 128>>>();
    conv_kernel<<<dim3(Tn / 32, Bn), 256>>>(bias, out);
}